// round 2
// baseline (speedup 1.0000x reference)
#include <cuda_runtime.h>
#include <cuda_bf16.h>
#include <cstddef>

// Problem constants
#define NB    2
#define SLEN  2048
#define EMB   1024          // H=16, D=64
#define CH    256           // number of S-chunks for the column-sum
#define SPER  (SLEN / CH)   // 8 rows per chunk

// Scratch (no allocations allowed) — ~2 MB total
__device__ float g_part[CH][NB][EMB];   // partial column sums of `values`
__device__ float g_t[NB][EMB];          // t = blockdiag(Wv) @ sv
__device__ float g_y[NB][EMB];          // y = Wo @ t + bo

// ---------------------------------------------------------------------------
// K1: partial column sums over S.  Grid (CH, NB) x 256 threads, float4.
// Each block reads SPER=8 contiguous rows (32 KB), fully unrolled -> MLP=8.
// 512 blocks total -> fills the chip.
// ---------------------------------------------------------------------------
__global__ void k_colsum_partial(const float* __restrict__ vals)
{
    const int n = blockIdx.y;
    const int c = blockIdx.x;
    const int t = threadIdx.x;  // 0..255 -> float4 lane over EMB

    const float4* __restrict__ base =
        (const float4*)(vals + (size_t)n * SLEN * EMB + (size_t)c * SPER * EMB);

    float4 acc = make_float4(0.f, 0.f, 0.f, 0.f);
    #pragma unroll
    for (int s = 0; s < SPER; ++s) {
        float4 v = __ldg(&base[s * (EMB / 4) + t]);
        acc.x += v.x; acc.y += v.y; acc.z += v.z; acc.w += v.w;
    }
    ((float4*)g_part[c][n])[t] = acc;
}

// ---------------------------------------------------------------------------
// K2: finish sv reduction (fixed order -> deterministic) and apply the
// block-diagonal per-head Wv: t[n, h*64+d] = sum_d' Wv[d,d'] * sv[n, h*64+d'].
// Grid (NB) x 1024 threads.
// ---------------------------------------------------------------------------
__global__ void k_wv(const float* __restrict__ Wv)
{
    const int n = blockIdx.x;
    const int e = threadIdx.x;  // 0..1023

    float sv = 0.f;
    #pragma unroll 8
    for (int c = 0; c < CH; ++c) sv += g_part[c][n][e];

    __shared__ float s_sv[EMB];
    s_sv[e] = sv;
    __syncthreads();

    const int h = e >> 6;
    const int d = e & 63;
    const float* __restrict__ wrow = Wv + d * 64;     // Wv[d, :]
    const float* __restrict__ svh  = s_sv + h * 64;

    float acc = 0.f;
    #pragma unroll 16
    for (int dp = 0; dp < 64; ++dp) acc += wrow[dp] * svh[dp];

    g_t[n][e] = acc;
}

// ---------------------------------------------------------------------------
// K3: y[n][e] = Wo[e,:] . t[n] + bo[e] for BOTH batches from one Wo-row read.
// One warp per output element e; lanes stride the row with float4.
// 1024 warps = 128 blocks x 256 threads.
// ---------------------------------------------------------------------------
__global__ void k_wo(const float* __restrict__ Wo, const float* __restrict__ bo)
{
    const int e    = blockIdx.x * 8 + (threadIdx.x >> 5);  // 0..1023
    const int lane = threadIdx.x & 31;

    const float4* __restrict__ row = (const float4*)(Wo + (size_t)e * EMB);
    const float4* __restrict__ t0  = (const float4*)g_t[0];
    const float4* __restrict__ t1  = (const float4*)g_t[1];

    float a0 = 0.f, a1 = 0.f;
    #pragma unroll
    for (int i = lane; i < EMB / 4; i += 32) {
        float4 w = __ldg(&row[i]);
        float4 b = t0[i];
        float4 c = t1[i];
        a0 += w.x * b.x + w.y * b.y + w.z * b.z + w.w * b.w;
        a1 += w.x * c.x + w.y * c.y + w.z * c.z + w.w * c.w;
    }
    #pragma unroll
    for (int o = 16; o; o >>= 1) {
        a0 += __shfl_xor_sync(0xFFFFFFFFu, a0, o);
        a1 += __shfl_xor_sync(0xFFFFFFFFu, a1, o);
    }

    if (lane == 0) {
        const float be = bo[e];
        g_y[0][e] = a0 + be;
        g_y[1][e] = a1 + be;
    }
}

// ---------------------------------------------------------------------------
// K4: broadcast y[n] to every sequence row.  Grid (256, NB) x 256, float4
// stores; each block writes 8 rows (32 KB). 512 blocks -> fills the chip.
// ---------------------------------------------------------------------------
__global__ void k_broadcast(float* __restrict__ out)
{
    const int n = blockIdx.y;
    const int t = threadIdx.x;

    const float4 v = ((const float4*)g_y[n])[t];

    float4* __restrict__ dst =
        (float4*)(out + (size_t)n * SLEN * EMB + (size_t)blockIdx.x * 8 * EMB);
    #pragma unroll
    for (int s = 0; s < 8; ++s)
        dst[s * (EMB / 4) + t] = v;
}

// ---------------------------------------------------------------------------
// Inputs (metadata order): 0=values 1=keys 2=queries 3=mask 4=Wv 5=Wk 6=Wq
//                          7=Wo 8=bo.   Output: float32 [2, 2048, 1024].
// ---------------------------------------------------------------------------
extern "C" void kernel_launch(void* const* d_in, const int* in_sizes, int n_in,
                              void* d_out, int out_size)
{
    const float* values = (const float*)d_in[0];
    const float* Wv     = (const float*)d_in[4];
    const float* Wo     = (const float*)d_in[7];
    const float* bo     = (const float*)d_in[8];
    float*       out    = (float*)d_out;

    k_colsum_partial<<<dim3(CH, NB), 256>>>(values);
    k_wv<<<NB, EMB>>>(Wv);
    k_wo<<<EMB / 8, 256>>>(Wo, bo);
    k_broadcast<<<dim3(SLEN / 8, NB), 256>>>(out);
}

// round 4
// speedup vs baseline: 1.4642x; 1.4642x over previous
#include <cuda_runtime.h>
#include <cuda_bf16.h>
#include <cstddef>

// Problem constants
#define NB     2
#define SLEN   2048
#define EMB    1024          // H=16, D=64
#define CH     64            // S-chunks for the column-sum
#define SPER   (SLEN / CH)   // 32 rows per chunk
#define ECH    32            // e-chunk width for KB (32 floats = 128B segments)
#define SSPLIT 8             // row-splits for KB
#define SROWS  (SLEN / SSPLIT)

// Scratch (__device__ globals; no allocation)
__device__ float g_part[CH][NB][EMB];   // partial column sums of `values`
__device__ float g_t[NB][EMB];          // t = blockdiag(Wv) @ sv
__device__ int   g_cnt[NB];             // ticket counters (zero-init; reset by tail)

// ---------------------------------------------------------------------------
// KA: column-sum partials + ticket-gated tail.
// Grid (CH, NB) x 256 threads. Main phase: each block sums 32 contiguous rows
// (128 KB) with float4 lanes. The LAST arriving block per batch reduces all 64
// partials in fixed order (deterministic) and applies the per-head Wv matvec.
// ---------------------------------------------------------------------------
__global__ void k_sum_wv(const float* __restrict__ vals,
                         const float* __restrict__ Wv)
{
    const int n = blockIdx.y;
    const int c = blockIdx.x;
    const int t = threadIdx.x;  // 0..255 -> float4 lane over EMB

    // ---- phase 1: partial sum of 32 rows ----
    const float4* __restrict__ base =
        (const float4*)(vals + (size_t)n * SLEN * EMB + (size_t)c * SPER * EMB);

    float4 acc = make_float4(0.f, 0.f, 0.f, 0.f);
    #pragma unroll 8
    for (int s = 0; s < SPER; ++s) {
        float4 v = __ldg(&base[s * (EMB / 4) + t]);
        acc.x += v.x; acc.y += v.y; acc.z += v.z; acc.w += v.w;
    }
    ((float4*)g_part[c][n])[t] = acc;

    // ---- ticket: last block of this batch finishes the job ----
    __threadfence();
    __syncthreads();
    __shared__ int s_ticket;
    if (t == 0) s_ticket = atomicAdd(&g_cnt[n], 1);
    __syncthreads();
    if (s_ticket != CH - 1) return;

    // ---- phase 2 (tail block only): reduce partials -> sv ----
    float4 sv = make_float4(0.f, 0.f, 0.f, 0.f);
    #pragma unroll 8
    for (int c2 = 0; c2 < CH; ++c2) {
        float4 p = __ldcg(&((const float4*)g_part[c2][n])[t]);  // bypass L1
        sv.x += p.x; sv.y += p.y; sv.z += p.z; sv.w += p.w;
    }
    __shared__ __align__(16) float s_sv[EMB];
    ((float4*)s_sv)[t] = sv;
    __syncthreads();

    // ---- phase 3: t[e] = Wv[d,:] . sv[h*64 : h*64+64],  e = 4t..4t+3 ----
    const int e0 = 4 * t;
    const int h  = e0 >> 6;
    const int d0 = e0 & 63;
    const float* __restrict__ svh = s_sv + (h << 6);

    float a0 = 0.f, a1 = 0.f, a2 = 0.f, a3 = 0.f;
    #pragma unroll 16
    for (int dp = 0; dp < 64; ++dp) {
        const float s = svh[dp];
        a0 += __ldg(&Wv[(d0 + 0) * 64 + dp]) * s;
        a1 += __ldg(&Wv[(d0 + 1) * 64 + dp]) * s;
        a2 += __ldg(&Wv[(d0 + 2) * 64 + dp]) * s;
        a3 += __ldg(&Wv[(d0 + 3) * 64 + dp]) * s;
    }
    ((float4*)g_t[n])[t] = make_float4(a0, a1, a2, a3);

    // reset counter for the next graph replay (kernel boundary orders this)
    if (t == 0) g_cnt[n] = 0;
}

// ---------------------------------------------------------------------------
// KB: fused Wo-matvec + broadcast.
// Grid (ECH chunks = 32, SSPLIT = 8) x 256 threads. Each block:
//   1) computes y[n][e0:e0+32] for BOTH batches (warp w -> 4 e's, lanes stride
//      the 4 KB Wo row with float4; Wo chunk is L2-hot across the 8 replicas)
//   2) writes its 128 B y-segment to its 256 rows per batch:
//      thread -> (row-group, seg), 16 independent STG.128 per thread.
// ---------------------------------------------------------------------------
__global__ void k_wo_bcast(const float* __restrict__ Wo,
                           const float* __restrict__ bo,
                           float* __restrict__ out)
{
    const int ech  = blockIdx.x;          // 0..31
    const int ss   = blockIdx.y;          // 0..SSPLIT-1
    const int tid  = threadIdx.x;
    const int w    = tid >> 5;            // warp 0..7
    const int lane = tid & 31;

    __shared__ float4 s_y4[NB][ECH / 4];  // natively float4 -> 16B aligned
    float* s_y0 = (float*)s_y4[0];
    float* s_y1 = (float*)s_y4[1];

    // ---- compute y chunk: warp w handles e = ech*32 + 4w .. +3 ----
    const int ebase = ech * ECH + 4 * w;
    const float4* __restrict__ t0 = (const float4*)g_t[0];
    const float4* __restrict__ t1 = (const float4*)g_t[1];

    #pragma unroll
    for (int j = 0; j < 4; ++j) {
        const int e = ebase + j;
        const float4* __restrict__ row = (const float4*)(Wo + (size_t)e * EMB);
        float a0 = 0.f, a1 = 0.f;
        #pragma unroll
        for (int i = lane; i < EMB / 4; i += 32) {
            float4 wv = __ldg(&row[i]);
            float4 b  = t0[i];
            float4 cc = t1[i];
            a0 += wv.x * b.x  + wv.y * b.y  + wv.z * b.z  + wv.w * b.w;
            a1 += wv.x * cc.x + wv.y * cc.y + wv.z * cc.z + wv.w * cc.w;
        }
        #pragma unroll
        for (int o = 16; o; o >>= 1) {
            a0 += __shfl_xor_sync(0xFFFFFFFFu, a0, o);
            a1 += __shfl_xor_sync(0xFFFFFFFFu, a1, o);
        }
        if (lane == 0) {
            const float be = __ldg(&bo[e]);
            s_y0[4 * w + j] = a0 + be;
            s_y1[4 * w + j] = a1 + be;
        }
    }
    __syncthreads();

    // ---- broadcast: write the 128 B segment to 256 rows x 2 batches ----
    const int rg  = tid >> 3;   // row-group 0..31
    const int seg = tid & 7;    // float4 segment 0..7 within the 32-float chunk

    const float4 v0 = s_y4[0][seg];
    const float4 v1 = s_y4[1][seg];

    float4* __restrict__ o4 = (float4*)out;
    const size_t colbase = (size_t)ech * (ECH / 4) + seg;   // in float4 units
    const size_t row0    = (size_t)ss * SROWS + rg;

    #pragma unroll
    for (int r = 0; r < SROWS / 32; ++r) {                  // 8 iterations
        const size_t rrow = row0 + (size_t)r * 32;
        o4[(0 * SLEN + rrow) * (EMB / 4) + colbase] = v0;
        o4[(1 * SLEN + rrow) * (EMB / 4) + colbase] = v1;
    }
}

// ---------------------------------------------------------------------------
// Inputs (metadata order): 0=values 1=keys 2=queries 3=mask 4=Wv 5=Wk 6=Wq
//                          7=Wo 8=bo.   Output: float32 [2, 2048, 1024].
// ---------------------------------------------------------------------------
extern "C" void kernel_launch(void* const* d_in, const int* in_sizes, int n_in,
                              void* d_out, int out_size)
{
    const float* values = (const float*)d_in[0];
    const float* Wv     = (const float*)d_in[4];
    const float* Wo     = (const float*)d_in[7];
    const float* bo     = (const float*)d_in[8];
    float*       out    = (float*)d_out;

    k_sum_wv<<<dim3(CH, NB), 256>>>(values, Wv);
    k_wo_bcast<<<dim3(EMB / ECH, SSPLIT), 256>>>(Wo, bo, out);
}

// round 5
// speedup vs baseline: 2.5295x; 1.7275x over previous
#include <cuda_runtime.h>
#include <cuda_bf16.h>
#include <cstddef>

// Problem constants
#define NB    2
#define SLEN  2048
#define EMB   1024           // H=16, D=64
#define NBLK  256            // persistent grid (co-resident: 148 SMs x 2)
#define THR   256
#define CPN   128            // chunks per batch (NBLK / NB)
#define RPB   (SLEN / CPN)   // 16 rows per chunk

// Scratch (__device__ globals; no allocation). Zero-init counters/flags;
// the last exiting block resets them -> graph-replay safe.
__device__ float g_part[NB][CPN][EMB];  // per-chunk column-sum partials
__device__ float g_t[NB][EMB];          // t = blockdiag(Wv) @ sv
__device__ float g_y[NB][EMB];          // y = Wo @ t + bo
__device__ int   g_c1, g_c2, g_c3, g_ce;
__device__ volatile int g_f1, g_f2, g_f3;

// Grid-wide barrier: arrive (ticket), last sets flag, rest spin (tid 0 only).
__device__ __forceinline__ void gbar(int* cnt, volatile int* flag)
{
    __syncthreads();
    if (threadIdx.x == 0) {
        __threadfence();                       // publish this block's writes
        if (atomicAdd(cnt, 1) == NBLK - 1) {
            *flag = 1;
        } else {
            while (*flag == 0) { __nanosleep(64); }
        }
        __threadfence();
    }
    __syncthreads();
}

__global__ void __launch_bounds__(THR, 2)
k_fused(const float* __restrict__ vals,
        const float* __restrict__ Wv,
        const float* __restrict__ Wo,
        const float* __restrict__ bo,
        float*       __restrict__ out)
{
    const int b   = blockIdx.x;
    const int tid = threadIdx.x;

    // ======================= P1: column-sum partials =======================
    {
        const int n = b >> 7;          // batch
        const int c = b & (CPN - 1);   // chunk
        const float4* __restrict__ base =
            (const float4*)(vals + (size_t)n * SLEN * EMB + (size_t)c * RPB * EMB);

        float4 acc = make_float4(0.f, 0.f, 0.f, 0.f);
        #pragma unroll
        for (int s = 0; s < RPB; ++s) {
            float4 v = __ldg(&base[s * (EMB / 4) + tid]);
            acc.x += v.x; acc.y += v.y; acc.z += v.z; acc.w += v.w;
        }
        ((float4*)g_part[n][c])[tid] = acc;
    }
    gbar(&g_c1, &g_f1);

    // ================= P2: reduce partials -> sv, apply Wv =================
    // 16 blocks: block r covers n = r>>3, e-range [seg*128, seg*128+128)
    // (two full heads). thread = (lane L over 32 float4 cols) x (c-split cs).
    if (b < 16) {
        const int n     = b >> 3;
        const int seg   = b & 7;
        const int ebase = seg * 128;
        const int L     = tid & 31;    // float4 lane within the 128-e range
        const int cs    = tid >> 5;    // 0..7 c-split

        float4 p = make_float4(0.f, 0.f, 0.f, 0.f);
        #pragma unroll
        for (int c = cs * 16; c < cs * 16 + 16; ++c) {
            float4 v = __ldcg(&((const float4*)g_part[n][c])[ebase / 4 + L]);
            p.x += v.x; p.y += v.y; p.z += v.z; p.w += v.w;
        }
        __shared__ float4 sp[8][32];
        __shared__ __align__(16) float s_sv[128];
        sp[cs][L] = p;
        __syncthreads();
        if (tid < 32) {
            float4 sv = sp[0][tid];
            #pragma unroll
            for (int j = 1; j < 8; ++j) {          // fixed order -> deterministic
                float4 v = sp[j][tid];
                sv.x += v.x; sv.y += v.y; sv.z += v.z; sv.w += v.w;
            }
            ((float4*)s_sv)[tid] = sv;
        }
        __syncthreads();
        if (tid < 128) {
            const int hloc = tid >> 6;             // which of the 2 heads
            const int d    = tid & 63;
            const float* __restrict__ wrow = Wv + d * 64;
            const float* __restrict__ svh  = s_sv + (hloc << 6);
            float acc = 0.f;
            #pragma unroll 16
            for (int dp = 0; dp < 64; ++dp) acc += wrow[dp] * svh[dp];
            g_t[n][ebase + tid] = acc;
        }
    }
    gbar(&g_c2, &g_f2);

    // ===================== P3: y = Wo @ t + bo (both n) =====================
    // 1024 warps (blocks 0..127), one warp per output element e; Wo read once.
    {
        const int gid = b * 8 + (tid >> 5);
        if (gid < EMB) {
            const int e    = gid;
            const int lane = tid & 31;
            const float4* __restrict__ row = (const float4*)(Wo + (size_t)e * EMB);
            const float4* __restrict__ t0  = (const float4*)g_t[0];
            const float4* __restrict__ t1  = (const float4*)g_t[1];

            float a0 = 0.f, a1 = 0.f;
            #pragma unroll
            for (int i = lane; i < EMB / 4; i += 32) {
                float4 w = __ldg(&row[i]);
                float4 x = __ldcg(&t0[i]);
                float4 z = __ldcg(&t1[i]);
                a0 += w.x * x.x + w.y * x.y + w.z * x.z + w.w * x.w;
                a1 += w.x * z.x + w.y * z.y + w.z * z.z + w.w * z.w;
            }
            #pragma unroll
            for (int o = 16; o; o >>= 1) {
                a0 += __shfl_xor_sync(0xFFFFFFFFu, a0, o);
                a1 += __shfl_xor_sync(0xFFFFFFFFu, a1, o);
            }
            if (lane == 0) {
                const float be = __ldg(&bo[e]);
                g_y[0][e] = a0 + be;
                g_y[1][e] = a1 + be;
            }
        }
    }
    gbar(&g_c3, &g_f3);

    // ===================== P4: broadcast y to all rows =====================
    {
        const int n = b >> 7;
        const int c = b & (CPN - 1);
        const float4 v = __ldcg(&((const float4*)g_y[n])[tid]);

        float4* __restrict__ dst =
            (float4*)(out + (size_t)n * SLEN * EMB + (size_t)c * RPB * EMB);
        #pragma unroll
        for (int s = 0; s < RPB; ++s)
            dst[s * (EMB / 4) + tid] = v;
    }

    // ======================= exit: reset for replay ========================
    __threadfence();
    __syncthreads();
    if (tid == 0) {
        if (atomicAdd(&g_ce, 1) == NBLK - 1) {
            g_c1 = 0; g_c2 = 0; g_c3 = 0; g_ce = 0;
            g_f1 = 0; g_f2 = 0; g_f3 = 0;
        }
    }
}

// ---------------------------------------------------------------------------
// Inputs (metadata order): 0=values 1=keys 2=queries 3=mask 4=Wv 5=Wk 6=Wq
//                          7=Wo 8=bo.   Output: float32 [2, 2048, 1024].
// ---------------------------------------------------------------------------
extern "C" void kernel_launch(void* const* d_in, const int* in_sizes, int n_in,
                              void* d_out, int out_size)
{
    const float* values = (const float*)d_in[0];
    const float* Wv     = (const float*)d_in[4];
    const float* Wo     = (const float*)d_in[7];
    const float* bo     = (const float*)d_in[8];
    float*       out    = (float*)d_out;

    k_fused<<<NBLK, THR>>>(values, Wv, Wo, bo, out);
}

// round 6
// speedup vs baseline: 2.7123x; 1.0723x over previous
#include <cuda_runtime.h>
#include <cuda_bf16.h>
#include <cstddef>

// Problem constants
#define NB    2
#define SLEN  2048
#define EMB   1024           // H=16, D=64
#define NBLK  256            // persistent grid (co-resident: 148 SMs x 2)
#define THR   256
#define CPN   128            // chunks per batch (NBLK / NB)
#define RPB   (SLEN / CPN)   // 16 rows per chunk

// Scratch (__device__ globals; no allocation). Zero-init counters/flags;
// the last exiting block resets them -> graph-replay safe.
__device__ float g_part[NB][CPN][EMB];  // per-chunk column-sum partials
__device__ float g_t[NB][EMB];          // t = blockdiag(Wv) @ sv
__device__ float g_y[NB][EMB];          // y = Wo @ t + bo
__device__ int   g_c1, g_c2, g_c3, g_ce;
__device__ volatile int g_f1, g_f2, g_f3;

// Grid-wide barrier: arrive (ticket), last sets flag, rest spin (tid 0 only).
__device__ __forceinline__ void gbar(int* cnt, volatile int* flag)
{
    __syncthreads();
    if (threadIdx.x == 0) {
        __threadfence();                       // publish this block's writes
        if (atomicAdd(cnt, 1) == NBLK - 1) {
            *flag = 1;
        } else {
            while (*flag == 0) { __nanosleep(32); }
        }
        __threadfence();
    }
    __syncthreads();
}

__global__ void __launch_bounds__(THR, 2)
k_fused(const float* __restrict__ vals,
        const float* __restrict__ Wv,
        const float* __restrict__ Wo,
        const float* __restrict__ bo,
        float*       __restrict__ out)
{
    const int b   = blockIdx.x;
    const int tid = threadIdx.x;

    // ======================= P1: column-sum partials =======================
    {
        const int n = b >> 7;          // batch
        const int c = b & (CPN - 1);   // chunk
        const float4* __restrict__ base =
            (const float4*)(vals + (size_t)n * SLEN * EMB + (size_t)c * RPB * EMB);

        float4 acc = make_float4(0.f, 0.f, 0.f, 0.f);
        #pragma unroll
        for (int s = 0; s < RPB; ++s) {
            float4 v = __ldg(&base[s * (EMB / 4) + tid]);
            acc.x += v.x; acc.y += v.y; acc.z += v.z; acc.w += v.w;
        }
        ((float4*)g_part[n][c])[tid] = acc;
    }
    gbar(&g_c1, &g_f1);

    // ================= P2: reduce partials -> sv, apply Wv =================
    // 32 blocks: block covers (n = b>>4, head h = b&15), e-range [h*64, h*64+64).
    // Stage A: 16-way c-split x 16 float4 cols. Stage B: fixed-order tree.
    // Stage C: 64 threads do the 64x64 Wv matvec for this head.
    if (b < 32) {
        const int n  = b >> 4;
        const int h  = b & 15;
        const int L  = tid & 15;       // float4 col within the head (64 floats)
        const int cs = tid >> 4;       // 0..15 c-split (8 chunks each)

        float4 p = make_float4(0.f, 0.f, 0.f, 0.f);
        #pragma unroll
        for (int k = 0; k < 8; ++k) {
            const int c = cs * 8 + k;
            float4 v = __ldcg(&((const float4*)g_part[n][c])[h * 16 + L]);
            p.x += v.x; p.y += v.y; p.z += v.z; p.w += v.w;
        }
        __shared__ float4 sp[16][16];
        __shared__ float4 s_sv4[16];
        sp[cs][L] = p;
        __syncthreads();
        if (tid < 16) {
            float4 sv = sp[0][tid];
            #pragma unroll
            for (int j = 1; j < 16; ++j) {         // fixed order -> deterministic
                float4 v = sp[j][tid];
                sv.x += v.x; sv.y += v.y; sv.z += v.z; sv.w += v.w;
            }
            s_sv4[tid] = sv;
        }
        __syncthreads();
        if (tid < 64) {
            const float* __restrict__ svh  = (const float*)s_sv4;
            const float* __restrict__ wrow = Wv + tid * 64;
            float acc = 0.f;
            #pragma unroll 16
            for (int dp = 0; dp < 64; ++dp) acc += __ldg(&wrow[dp]) * svh[dp];
            g_t[n][h * 64 + tid] = acc;
        }
    }
    gbar(&g_c2, &g_f2);

    // ===================== P3: y = Wo @ t + bo (both n) =====================
    // ALL 256 blocks, 4 e-rows each; 2 warps per e split the 1024-wide dot.
    {
        const int e0   = b * 4;
        const int w    = tid >> 5;       // warp 0..7
        const int lane = tid & 31;
        const int el   = w >> 1;         // e-local 0..3
        const int half = w & 1;          // j-range half

        const int e = e0 + el;
        const float4* __restrict__ row =
            (const float4*)(Wo + (size_t)e * EMB) + half * 128;
        const float4* __restrict__ t0 = (const float4*)g_t[0] + half * 128;
        const float4* __restrict__ t1 = (const float4*)g_t[1] + half * 128;

        float a0 = 0.f, a1 = 0.f;
        #pragma unroll
        for (int i = lane; i < 128; i += 32) {
            float4 wv = __ldg(&row[i]);
            float4 x  = __ldcg(&t0[i]);
            float4 z  = __ldcg(&t1[i]);
            a0 += wv.x * x.x + wv.y * x.y + wv.z * x.z + wv.w * x.w;
            a1 += wv.x * z.x + wv.y * z.y + wv.z * z.z + wv.w * z.w;
        }
        #pragma unroll
        for (int o = 16; o; o >>= 1) {
            a0 += __shfl_xor_sync(0xFFFFFFFFu, a0, o);
            a1 += __shfl_xor_sync(0xFFFFFFFFu, a1, o);
        }

        __shared__ float s_part[NB][4][2];
        if (lane == 0) {
            s_part[0][el][half] = a0;
            s_part[1][el][half] = a1;
        }
        __syncthreads();
        if (tid < 8) {                    // n = tid>>2, e-local = tid&3
            const int nn = tid >> 2;
            const int ee = tid & 3;
            g_y[nn][e0 + ee] = s_part[nn][ee][0] + s_part[nn][ee][1]
                             + __ldg(&bo[e0 + ee]);
        }
    }
    gbar(&g_c3, &g_f3);

    // ===================== P4: broadcast y to all rows =====================
    {
        const int n = b >> 7;
        const int c = b & (CPN - 1);
        const float4 v = __ldcg(&((const float4*)g_y[n])[tid]);

        float4* __restrict__ dst =
            (float4*)(out + (size_t)n * SLEN * EMB + (size_t)c * RPB * EMB);
        #pragma unroll
        for (int s = 0; s < RPB; ++s)
            dst[s * (EMB / 4) + tid] = v;
    }

    // ======================= exit: reset for replay ========================
    __threadfence();
    __syncthreads();
    if (tid == 0) {
        if (atomicAdd(&g_ce, 1) == NBLK - 1) {
            g_c1 = 0; g_c2 = 0; g_c3 = 0; g_ce = 0;
            g_f1 = 0; g_f2 = 0; g_f3 = 0;
        }
    }
}

// ---------------------------------------------------------------------------
// Inputs (metadata order): 0=values 1=keys 2=queries 3=mask 4=Wv 5=Wk 6=Wq
//                          7=Wo 8=bo.   Output: float32 [2, 2048, 1024].
// ---------------------------------------------------------------------------
extern "C" void kernel_launch(void* const* d_in, const int* in_sizes, int n_in,
                              void* d_out, int out_size)
{
    const float* values = (const float*)d_in[0];
    const float* Wv     = (const float*)d_in[4];
    const float* Wo     = (const float*)d_in[7];
    const float* bo     = (const float*)d_in[8];
    float*       out    = (float*)d_out;

    k_fused<<<NBLK, THR>>>(values, Wv, Wo, bo, out);
}

// round 7
// speedup vs baseline: 2.8009x; 1.0327x over previous
#include <cuda_runtime.h>
#include <cuda_bf16.h>
#include <cstddef>

// Problem constants
#define NB    2
#define SLEN  2048
#define EMB   1024            // H=16, D=64
#define NBLK  256             // persistent grid (co-resident: 148 SMs x 2)
#define THR   512
#define CPN   256             // partial chunks per batch (8 rows each)
#define RPB   8               // rows per partial chunk

// Scratch (__device__ globals; no allocation). Zero-init counters/flags;
// the last exiting block resets them -> graph-replay safe.
__device__ float g_part[NB][CPN][EMB];  // per-chunk column-sum partials (8 MB)
__device__ float g_t[NB][EMB];          // t = blockdiag(Wv) @ sv
__device__ float g_y[NB][EMB];          // y = Wo @ t + bo
__device__ int   g_c1, g_c2, g_c3, g_ce;
__device__ volatile int g_f1, g_f2, g_f3;

// Grid-wide barrier: arrive (ticket), last sets flag, rest spin (tid 0 only).
__device__ __forceinline__ void gbar(int* cnt, volatile int* flag)
{
    __syncthreads();
    if (threadIdx.x == 0) {
        __threadfence();                       // publish this block's writes
        if (atomicAdd(cnt, 1) == NBLK - 1) {
            *flag = 1;
        } else {
            while (*flag == 0) { __nanosleep(32); }
        }
        __threadfence();
    }
    __syncthreads();
}

__global__ void __launch_bounds__(THR, 2)
k_fused(const float* __restrict__ vals,
        const float* __restrict__ Wv,
        const float* __restrict__ Wo,
        const float* __restrict__ bo,
        float*       __restrict__ out)
{
    const int b   = blockIdx.x;
    const int tid = threadIdx.x;

    // ======================= P1: column-sum partials =======================
    // Block b: batch n = b>>7, base chunk 2*(b&127); halves of the block do
    // two adjacent 8-row chunks. 131K threads streaming, MLP=8 per thread.
    {
        const int n    = b >> 7;
        const int c    = ((b & 127) << 1) + (tid >> 8);  // chunk 0..255
        const int col  = tid & 255;                      // float4 lane
        const float4* __restrict__ base =
            (const float4*)(vals + (size_t)n * SLEN * EMB + (size_t)c * RPB * EMB);

        float4 acc = make_float4(0.f, 0.f, 0.f, 0.f);
        #pragma unroll
        for (int s = 0; s < RPB; ++s) {
            float4 v = __ldg(&base[s * (EMB / 4) + col]);
            acc.x += v.x; acc.y += v.y; acc.z += v.z; acc.w += v.w;
        }
        ((float4*)g_part[n][c])[col] = acc;
    }
    gbar(&g_c1, &g_f1);

    // ================= P2: reduce partials -> sv, apply Wv =================
    // 32 blocks: block = (n = b>>4, head h = b&15). 512 threads =
    // 32 c-splits (8 chunks each) x 16 float4 cols. Fixed-order tree.
    if (b < 32) {
        const int n  = b >> 4;
        const int h  = b & 15;
        const int L  = tid & 15;       // float4 col within the head
        const int cs = tid >> 4;       // 0..31 c-split

        float4 p = make_float4(0.f, 0.f, 0.f, 0.f);
        #pragma unroll
        for (int k = 0; k < 8; ++k) {
            const int c = cs * 8 + k;
            float4 v = __ldcg(&((const float4*)g_part[n][c])[h * 16 + L]);
            p.x += v.x; p.y += v.y; p.z += v.z; p.w += v.w;
        }
        __shared__ float4 sp[32][16];
        __shared__ float4 s_sv4[16];
        sp[cs][L] = p;
        __syncthreads();
        if (tid < 16) {
            float4 sv = sp[0][tid];
            #pragma unroll
            for (int j = 1; j < 32; ++j) {         // fixed order -> deterministic
                float4 v = sp[j][tid];
                sv.x += v.x; sv.y += v.y; sv.z += v.z; sv.w += v.w;
            }
            s_sv4[tid] = sv;
        }
        __syncthreads();
        if (tid < 64) {
            const float* __restrict__ svh  = (const float*)s_sv4;
            const float* __restrict__ wrow = Wv + tid * 64;
            float acc = 0.f;
            #pragma unroll 16
            for (int dp = 0; dp < 64; ++dp) acc += __ldg(&wrow[dp]) * svh[dp];
            g_t[n][h * 64 + tid] = acc;
        }
    }
    gbar(&g_c2, &g_f2);

    // ===================== P3: y = Wo @ t + bo (both n) =====================
    // ALL 256 blocks, 4 e-rows each; 4 warps per e split the 1024-wide dot.
    {
        const int e0   = b * 4;
        const int w    = tid >> 5;       // warp 0..15
        const int lane = tid & 31;
        const int el   = w >> 2;         // e-local 0..3
        const int q    = w & 3;          // quarter 0..3 (64 float4 each)

        const int e = e0 + el;
        const float4* __restrict__ row =
            (const float4*)(Wo + (size_t)e * EMB) + q * 64;
        const float4* __restrict__ t0 = (const float4*)g_t[0] + q * 64;
        const float4* __restrict__ t1 = (const float4*)g_t[1] + q * 64;

        float a0 = 0.f, a1 = 0.f;
        #pragma unroll
        for (int i = lane; i < 64; i += 32) {
            float4 wv = __ldg(&row[i]);
            float4 x  = __ldcg(&t0[i]);
            float4 z  = __ldcg(&t1[i]);
            a0 += wv.x * x.x + wv.y * x.y + wv.z * x.z + wv.w * x.w;
            a1 += wv.x * z.x + wv.y * z.y + wv.z * z.z + wv.w * z.w;
        }
        #pragma unroll
        for (int o = 16; o; o >>= 1) {
            a0 += __shfl_xor_sync(0xFFFFFFFFu, a0, o);
            a1 += __shfl_xor_sync(0xFFFFFFFFu, a1, o);
        }

        __shared__ float s_part[NB][4][4];
        if (lane == 0) {
            s_part[0][el][q] = a0;
            s_part[1][el][q] = a1;
        }
        __syncthreads();
        if (tid < 8) {                    // n = tid>>2, e-local = tid&3
            const int nn = tid >> 2;
            const int ee = tid & 3;
            g_y[nn][e0 + ee] = ((s_part[nn][ee][0] + s_part[nn][ee][1])
                              + (s_part[nn][ee][2] + s_part[nn][ee][3]))
                             + __ldg(&bo[e0 + ee]);
        }
    }
    gbar(&g_c3, &g_f3);

    // ===================== P4: broadcast y to all rows =====================
    // Block b: batch n = b>>7, 16-row slab; halves of the block do 8 rows each.
    {
        const int n    = b >> 7;
        const int c    = b & 127;                     // 16-row slab
        const int half = tid >> 8;
        const int col  = tid & 255;
        const float4 v = __ldcg(&((const float4*)g_y[n])[col]);

        float4* __restrict__ dst =
            (float4*)(out + (size_t)n * SLEN * EMB
                          + ((size_t)c * 16 + half * 8) * EMB);
        #pragma unroll
        for (int s = 0; s < 8; ++s)
            dst[s * (EMB / 4) + col] = v;
    }

    // ======================= exit: reset for replay ========================
    __threadfence();
    __syncthreads();
    if (tid == 0) {
        if (atomicAdd(&g_ce, 1) == NBLK - 1) {
            g_c1 = 0; g_c2 = 0; g_c3 = 0; g_ce = 0;
            g_f1 = 0; g_f2 = 0; g_f3 = 0;
        }
    }
}

// ---------------------------------------------------------------------------
// Inputs (metadata order): 0=values 1=keys 2=queries 3=mask 4=Wv 5=Wk 6=Wq
//                          7=Wo 8=bo.   Output: float32 [2, 2048, 1024].
// ---------------------------------------------------------------------------
extern "C" void kernel_launch(void* const* d_in, const int* in_sizes, int n_in,
                              void* d_out, int out_size)
{
    const float* values = (const float*)d_in[0];
    const float* Wv     = (const float*)d_in[4];
    const float* Wo     = (const float*)d_in[7];
    const float* bo     = (const float*)d_in[8];
    float*       out    = (float*)d_out;

    k_fused<<<NBLK, THR>>>(values, Wv, Wo, bo, out);
}